// round 14
// baseline (speedup 1.0000x reference)
#include <cuda_runtime.h>
#include <cuda_bf16.h>
#include <cuda_fp16.h>
#include <math.h>

#define NN 50000
#define EE 800000
#define ETOT (EE + NN)
#define NB 49              // ceil(NN/1024)
#define EPS 1e-5f
#define GB1 782            // gemm1 blocks = ceil(NN/64)
#define EB  3321           // edge blocks = ceil(ETOT/256)

// ---------------- device scratch ----------------
__device__ float   d_bufA[NN * 64];
__device__ float   d_bufB[NN * 64];
__device__ float   d_bufC[NN * 64];
__device__ __half2 d_h16[NN * 32];
__device__ float   d_es[NN * 2];
__device__ float   d_ed[NN * 2];
__device__ float   d_pe[ETOT * 2];   // per-edge exp (float2 for H2, float for H1)
__device__ int     d_rowptr[NN + 1];
__device__ int     d_cursor[NN];
__device__ int2    d_cr[ETOT];

// zero-blob: [cnt NN ints][bnacc 320 floats][lookback NB u64][3 counters + pad]
#define ZBYTES (NN * 4 + 320 * 4 + NB * 8 + 16)
__device__ unsigned long long d_zblob[(ZBYTES + 7) / 8];
#define D_CNT   ((int*)d_zblob)
#define D_LOOK  ((unsigned long long*)((char*)d_zblob + NN * 4 + 320 * 4))
#define D_CTR   ((int*)((char*)d_zblob + NN * 4 + 320 * 4 + NB * 8))

__device__ __forceinline__ float lrelu(float x) { return fmaxf(x, 0.2f * x); }

// ------- GEMM body (R4-proven scalar core) + BN input + es/ed + fp16-copy epilogue --
template<int K, int NC, bool BN, int H>
__device__ __forceinline__ void gemm_body(
    int bid,
    const float* __restrict__ X, const float* __restrict__ W,
    const float* __restrict__ asv, const float* __restrict__ adv,
    const float* __restrict__ accIn, const float* __restrict__ g,
    const float* __restrict__ be, float* __restrict__ Hout)
{
    constexpr int CT  = NC / 4;
    constexpr int RT  = 256 / CT;
    constexpr int RPB = RT * 4;
    __shared__ float sW[64 * NC];
    __shared__ float sX[RPB * 64];
    __shared__ float sS[BN ? K : 1];
    __shared__ float sT[BN ? K : 1];

    if (BN) {
        if (threadIdx.x < K) {
            float mu  = accIn[threadIdx.x] * (1.f / NN);
            float var = fmaf(-mu, mu, accIn[K + threadIdx.x] * (1.f / NN));
            float sc  = rsqrtf(var + EPS) * g[threadIdx.x];
            sS[threadIdx.x] = sc;
            sT[threadIdx.x] = be[threadIdx.x] - mu * sc;
        }
    }
    const int ct = threadIdx.x % CT;
    const int rt = threadIdx.x / CT;
    const int r0 = bid * RPB;
    const int row0 = rt * 4;
    float acc[4][4] = {};

    for (int kt = 0; kt < K; kt += 64) {
        __syncthreads();
#pragma unroll
        for (int i = threadIdx.x; i < 64 * NC / 4; i += 256) {
            reinterpret_cast<float4*>(sW)[i] =
                __ldg(reinterpret_cast<const float4*>(W) + (size_t)kt * (NC / 4) + i);
        }
#pragma unroll
        for (int i = threadIdx.x; i < RPB * 16; i += 256) {
            int r = i >> 4, c4 = i & 15;
            int gr = r0 + r;
            float4 v = make_float4(0.f, 0.f, 0.f, 0.f);
            if (gr < NN)
                v = *reinterpret_cast<const float4*>(X + (size_t)gr * K + kt + c4 * 4);
            if (BN) {
                int kk = kt + c4 * 4;
                v.x = fmaxf(fmaf(v.x, sS[kk + 0], sT[kk + 0]), 0.f);
                v.y = fmaxf(fmaf(v.y, sS[kk + 1], sT[kk + 1]), 0.f);
                v.z = fmaxf(fmaf(v.z, sS[kk + 2], sT[kk + 2]), 0.f);
                v.w = fmaxf(fmaf(v.w, sS[kk + 3], sT[kk + 3]), 0.f);
            }
            reinterpret_cast<float4*>(sX)[i] = v;
        }
        __syncthreads();
#pragma unroll 8
        for (int k = 0; k < 64; k += 4) {
            float4 wv0 = *reinterpret_cast<const float4*>(sW + (k + 0) * NC + ct * 4);
            float4 wv1 = *reinterpret_cast<const float4*>(sW + (k + 1) * NC + ct * 4);
            float4 wv2 = *reinterpret_cast<const float4*>(sW + (k + 2) * NC + ct * 4);
            float4 wv3 = *reinterpret_cast<const float4*>(sW + (k + 3) * NC + ct * 4);
#pragma unroll
            for (int i = 0; i < 4; i++) {
                float4 xv = *reinterpret_cast<const float4*>(sX + (row0 + i) * 64 + k);
                acc[i][0] = fmaf(xv.x, wv0.x, acc[i][0]);
                acc[i][1] = fmaf(xv.x, wv0.y, acc[i][1]);
                acc[i][2] = fmaf(xv.x, wv0.z, acc[i][2]);
                acc[i][3] = fmaf(xv.x, wv0.w, acc[i][3]);
                acc[i][0] = fmaf(xv.y, wv1.x, acc[i][0]);
                acc[i][1] = fmaf(xv.y, wv1.y, acc[i][1]);
                acc[i][2] = fmaf(xv.y, wv1.z, acc[i][2]);
                acc[i][3] = fmaf(xv.y, wv1.w, acc[i][3]);
                acc[i][0] = fmaf(xv.z, wv2.x, acc[i][0]);
                acc[i][1] = fmaf(xv.z, wv2.y, acc[i][1]);
                acc[i][2] = fmaf(xv.z, wv2.z, acc[i][2]);
                acc[i][3] = fmaf(xv.z, wv2.w, acc[i][3]);
                acc[i][0] = fmaf(xv.w, wv3.x, acc[i][0]);
                acc[i][1] = fmaf(xv.w, wv3.y, acc[i][1]);
                acc[i][2] = fmaf(xv.w, wv3.z, acc[i][2]);
                acc[i][3] = fmaf(xv.w, wv3.w, acc[i][3]);
            }
        }
    }

    float4 a_s = *reinterpret_cast<const float4*>(asv + ct * 4);
    float4 a_d = *reinterpret_cast<const float4*>(adv + ct * 4);
#pragma unroll
    for (int i = 0; i < 4; i++) {
        int gr = r0 + row0 + i;
        float ps = acc[i][0] * a_s.x + acc[i][1] * a_s.y + acc[i][2] * a_s.z + acc[i][3] * a_s.w;
        float pd = acc[i][0] * a_d.x + acc[i][1] * a_d.y + acc[i][2] * a_d.z + acc[i][3] * a_d.w;
        ps += __shfl_xor_sync(0xffffffffu, ps, 1);
        pd += __shfl_xor_sync(0xffffffffu, pd, 1);
        ps += __shfl_xor_sync(0xffffffffu, ps, 2);
        pd += __shfl_xor_sync(0xffffffffu, pd, 2);
        ps += __shfl_xor_sync(0xffffffffu, ps, 4);
        pd += __shfl_xor_sync(0xffffffffu, pd, 4);
        if (gr < NN) {
            float4 o = make_float4(acc[i][0], acc[i][1], acc[i][2], acc[i][3]);
            *reinterpret_cast<float4*>(Hout + (size_t)gr * NC + ct * 4) = o;
            int hbase = (NC == 64) ? (gr * 32 + ct * 2) : (gr * 16 + ct * 2);
            d_h16[hbase]     = __floats2half2_rn(acc[i][0], acc[i][1]);
            d_h16[hbase + 1] = __floats2half2_rn(acc[i][2], acc[i][3]);
            if ((ct & 7) == 0) {
                int head = (H == 2) ? (ct >> 3) : 0;
                d_es[gr * H + head] = ps;
                d_ed[gr * H + head] = pd;
            }
        }
    }
}

// fused gemm1 + degree count (independent block ranges, co-scheduled)
__global__ void __launch_bounds__(256) gemm1_count_k(
    const float* __restrict__ X, const float* __restrict__ W,
    const float* __restrict__ asv, const float* __restrict__ adv,
    float* __restrict__ Hout, const int* __restrict__ dst)
{
    if (blockIdx.x < GB1) {
        gemm_body<128, 64, false, 2>(blockIdx.x, X, W, asv, adv,
                                     nullptr, nullptr, nullptr, Hout);
    } else {
        int i = (blockIdx.x - GB1) * 256 + threadIdx.x;
        if (i < ETOT) {
            int d = (i < EE) ? __ldg(&dst[i]) : (i - EE);
            atomicAdd(&D_CNT[d], 1);
        }
    }
}

template<int K, int NC, bool BN, int H>
__global__ void __launch_bounds__(256) gemm_k(
    const float* __restrict__ X, const float* __restrict__ W,
    const float* __restrict__ asv, const float* __restrict__ adv,
    const float* __restrict__ accIn, const float* __restrict__ g,
    const float* __restrict__ be, float* __restrict__ Hout)
{
    gemm_body<K, NC, BN, H>(blockIdx.x, X, W, asv, adv, accIn, g, be, Hout);
}

// ---------- single-pass scan (decoupled lookback; 49 blocks, all resident) --------
__global__ void scan_k() {
    __shared__ int wsum[32];
    __shared__ int sprev;
    int bid  = blockIdx.x;
    int g    = bid * 1024 + threadIdx.x;
    int lane = threadIdx.x & 31, wid = threadIdx.x >> 5;
    int v = (g < NN) ? D_CNT[g] : 0;
    int x = v;
#pragma unroll
    for (int o = 1; o < 32; o <<= 1) {
        int t = __shfl_up_sync(0xffffffffu, x, o);
        if (lane >= o) x += t;
    }
    if (lane == 31) wsum[wid] = x;
    __syncthreads();
    if (wid == 0) {
        int w = wsum[lane];
#pragma unroll
        for (int o = 1; o < 32; o <<= 1) {
            int t = __shfl_up_sync(0xffffffffu, w, o);
            if (lane >= o) w += t;
        }
        wsum[lane] = w;
    }
    __syncthreads();
    int incl = x + (wid ? wsum[wid - 1] : 0);
    int total = wsum[31];

    if (threadIdx.x == 0) {
        atomicExch(&D_LOOK[bid], (unsigned long long)(unsigned)total | (1ull << 62));
        long long prev = 0;
        for (int j = bid - 1; j >= 0; ) {
            unsigned long long s;
            do { s = atomicAdd(&D_LOOK[j], 0ull); } while ((s >> 62) == 0);
            prev += (int)(unsigned)(s & 0xffffffffull);
            if ((s >> 62) == 2) break;
            j--;
        }
        atomicExch(&D_LOOK[bid],
                   (unsigned long long)(unsigned)(prev + total) | (2ull << 62));
        sprev = (int)prev;
    }
    __syncthreads();
    int inclg = incl + sprev;
    int excl  = inclg - v;
    if (g < NN) { d_rowptr[g] = excl; d_cursor[g] = excl; }
    if (g == NN - 1) d_rowptr[NN] = inclg;
}

// scatter + fused layer-1 exp (gemm1 already produced es/ed)
__global__ void scatter_k(const int* __restrict__ src, const int* __restrict__ dst) {
    int i = blockIdx.x * 256 + threadIdx.x;
    if (i >= ETOT) return;
    int s, d;
    if (i < EE) { s = __ldg(&src[i]); d = __ldg(&dst[i]); }
    else        { s = i - EE; d = s; }
    int pos = atomicAdd(&d_cursor[d], 1);
    d_cr[pos] = make_int2(s, d);
    const float2* es2 = reinterpret_cast<const float2*>(d_es);
    const float2* ed2 = reinterpret_cast<const float2*>(d_ed);
    float2 e  = __ldg(&es2[s]);
    float2 dd = __ldg(&ed2[d]);
    float2 p;
    p.x = __expf(lrelu(e.x + dd.x));
    p.y = __expf(lrelu(e.y + dd.y));
    reinterpret_cast<float2*>(d_pe)[pos] = p;
}

// ---------------- edge-parallel exp pass (layers 2,3) ----------------
template<int H>
__global__ void exp_k() {
    int i = blockIdx.x * 256 + threadIdx.x;
    if (i >= ETOT) return;
    int2 cr = __ldg(&d_cr[i]);
    if (H == 2) {
        const float2* es2 = reinterpret_cast<const float2*>(d_es);
        const float2* ed2 = reinterpret_cast<const float2*>(d_ed);
        float2 e = __ldg(&es2[cr.x]);
        float2 d = __ldg(&ed2[cr.y]);
        float2 p;
        p.x = __expf(lrelu(e.x + d.x));
        p.y = __expf(lrelu(e.y + d.y));
        reinterpret_cast<float2*>(d_pe)[i] = p;
    } else {
        d_pe[i] = __expf(lrelu(__ldg(&d_es[cr.x]) + __ldg(&d_ed[cr.y])));
    }
}

// -- GAT aggregation: dynamic warp scheduling (global balance) + fp16 gather + BN --
template<int H>
__global__ void __launch_bounds__(512) agg_k(const float* __restrict__ bias,
                                             float* __restrict__ out,
                                             float* __restrict__ accOut,
                                             int ctrIdx) {
    __shared__ float red[16][128];
    const unsigned FULL = 0xffffffffu;
    int w = threadIdx.x >> 5;
    int l = threadIdx.x & 31;

    if (H == 2) {
        const float2* pe2 = reinterpret_cast<const float2*>(d_pe);
        float2 bb = __ldg(reinterpret_cast<const float2*>(bias) + l);
        float bnS0 = 0.f, bnS1 = 0.f, bnQ0 = 0.f, bnQ1 = 0.f;
        for (;;) {
            int node;
            if (l == 0) node = atomicAdd(&D_CTR[ctrIdx], 1);
            node = __shfl_sync(FULL, node, 0);
            if (node >= NN) break;
            int beg = __ldg(&d_rowptr[node]);
            int end = __ldg(&d_rowptr[node + 1]);
            float dn = 0.f, a0 = 0.f, a1 = 0.f;
#pragma unroll 4
            for (int j = beg; j < end; j++) {
                int s = __ldg(&d_cr[j]).x;
                float2 p = __ldg(&pe2[j]);
                __half2 hh = __ldg(&d_h16[s * 32 + l]);
                float2 hf = __half22float2(hh);
                float pp = (l < 16) ? p.x : p.y;
                a0 = fmaf(pp, hf.x, a0);
                a1 = fmaf(pp, hf.y, a1);
                dn += pp;
            }
            float inv = 1.f / (dn + 1e-16f);
            float o0 = a0 * inv + bb.x;
            float o1 = a1 * inv + bb.y;
            reinterpret_cast<float2*>(out + (size_t)node * 64)[l] =
                make_float2(o0, o1);
            bnS0 += o0;  bnS1 += o1;
            bnQ0 = fmaf(o0, o0, bnQ0);
            bnQ1 = fmaf(o1, o1, bnQ1);
        }
        red[w][2 * l]          = bnS0;
        red[w][2 * l + 1]      = bnS1;
        red[w][64 + 2 * l]     = bnQ0;
        red[w][64 + 2 * l + 1] = bnQ1;
        __syncthreads();
        if (threadIdx.x < 128) {
            float s = 0.f;
#pragma unroll
            for (int i = 0; i < 16; i++) s += red[i][threadIdx.x];
            atomicAdd(&accOut[threadIdx.x], s);
        }
    } else {
        const __half* h16h = reinterpret_cast<const __half*>(d_h16);
        float bv = __ldg(bias + l);
        float bnS = 0.f, bnQ = 0.f;
        for (;;) {
            int node;
            if (l == 0) node = atomicAdd(&D_CTR[ctrIdx], 1);
            node = __shfl_sync(FULL, node, 0);
            if (node >= NN) break;
            int beg = __ldg(&d_rowptr[node]);
            int end = __ldg(&d_rowptr[node + 1]);
            float dn = 0.f, a = 0.f;
#pragma unroll 4
            for (int j = beg; j < end; j++) {
                int s = __ldg(&d_cr[j]).x;
                float p = __ldg(&d_pe[j]);
                float hv = __half2float(__ldg(&h16h[s * 32 + l]));
                a = fmaf(p, hv, a);
                dn += p;
            }
            float o = a / (dn + 1e-16f) + bv;
            out[(size_t)node * 32 + l] = o;
            bnS += o;
            bnQ = fmaf(o, o, bnQ);
        }
        red[w][l]      = bnS;
        red[w][32 + l] = bnQ;
        __syncthreads();
        if (threadIdx.x < 64) {
            float s = 0.f;
#pragma unroll
            for (int i = 0; i < 16; i++) s += red[i][threadIdx.x];
            atomicAdd(&accOut[threadIdx.x], s);
        }
    }
}

// final BN apply + ReLU -> out
__global__ void bnapply3_k(const float* __restrict__ X, const float* __restrict__ acc,
                           const float* __restrict__ g, const float* __restrict__ be,
                           float* __restrict__ Y) {
    int idx = blockIdx.x * 256 + threadIdx.x;
    if (idx >= NN * 32) return;
    int c = idx & 31;
    float mu  = acc[c] * (1.f / NN);
    float var = fmaf(-mu, mu, acc[32 + c] * (1.f / NN));
    float y = (X[idx] - mu) * rsqrtf(var + EPS) * g[c] + be[c];
    Y[idx] = fmaxf(y, 0.f);
}

// ---------------- launch ----------------
static inline int cdiv(int a, int b) { return (a + b - 1) / b; }

extern "C" void kernel_launch(void* const* d_in, const int* in_sizes, int n_in,
                              void* d_out, int out_size) {
    const float* x   = (const float*)d_in[0];
    const float* W1  = (const float*)d_in[1];
    const float* as1 = (const float*)d_in[2];
    const float* ad1 = (const float*)d_in[3];
    const float* b1  = (const float*)d_in[4];
    const float* g1  = (const float*)d_in[5];
    const float* be1 = (const float*)d_in[6];
    const float* W2  = (const float*)d_in[7];
    const float* as2 = (const float*)d_in[8];
    const float* ad2 = (const float*)d_in[9];
    const float* b2  = (const float*)d_in[10];
    const float* g2  = (const float*)d_in[11];
    const float* be2 = (const float*)d_in[12];
    const float* W3  = (const float*)d_in[13];
    const float* as3 = (const float*)d_in[14];
    const float* ad3 = (const float*)d_in[15];
    const float* b3  = (const float*)d_in[16];
    const float* g3  = (const float*)d_in[17];
    const float* be3 = (const float*)d_in[18];
    const int*   ei  = (const int*)d_in[19];
    const int* esrc = ei;
    const int* edst = ei + EE;

    float* bufA; cudaGetSymbolAddress((void**)&bufA, d_bufA);
    float* bufB; cudaGetSymbolAddress((void**)&bufB, d_bufB);
    float* bufC; cudaGetSymbolAddress((void**)&bufC, d_bufC);
    char*  zb;   cudaGetSymbolAddress((void**)&zb,   d_zblob);
    float* bnac = (float*)(zb + NN * 4);
    float* outp = (float*)d_out;

    const int aggBlocks  = 592;              // 4 blocks/SM, dynamic node pull
    const int edgeBlocks = EB;               // 3321

    cudaMemsetAsync(zb, 0, ZBYTES);

    // fused gemm1 + degree count (co-scheduled independent blocks)
    gemm1_count_k<<<GB1 + EB, 256>>>(x, W1, as1, ad1, bufB, edst);
    scan_k<<<NB, 1024>>>();
    scatter_k<<<edgeBlocks, 256>>>(esrc, edst);

    // layer 1 (exp already built in scatter)
    agg_k<2><<<aggBlocks, 512>>>(b1, bufC, bnac + 0, 0);

    // layer 2 (BN1+ReLU fused into X staging)
    gemm_k<64, 64, true, 2><<<cdiv(NN, 64), 256>>>(
        bufC, W2, as2, ad2, bnac + 0, g1, be1, bufB);
    exp_k<2><<<edgeBlocks, 256>>>();
    agg_k<2><<<aggBlocks, 512>>>(b2, bufC, bnac + 128, 1);

    // layer 3 (BN2+ReLU fused into X staging)
    gemm_k<64, 32, true, 1><<<cdiv(NN, 128), 256>>>(
        bufC, W3, as3, ad3, bnac + 128, g2, be2, bufA);
    exp_k<1><<<edgeBlocks, 256>>>();
    agg_k<1><<<aggBlocks, 512>>>(b3, bufC, bnac + 256, 2);
    bnapply3_k<<<cdiv(NN * 32, 256), 256>>>(bufC, bnac + 256, g3, be3, outp);
}

// round 15
// speedup vs baseline: 1.3528x; 1.3528x over previous
#include <cuda_runtime.h>
#include <cuda_bf16.h>
#include <cuda_fp16.h>
#include <math.h>

#define NN 50000
#define EE 800000
#define ETOT (EE + NN)
#define NB 49              // ceil(NN/1024)
#define EPS 1e-5f
#define GB1 782            // gemm1 blocks = ceil(NN/64)
#define EB  3321           // edge blocks = ceil(ETOT/256)

// ---------------- device scratch ----------------
__device__ float   d_bufA[NN * 64];
__device__ float   d_bufB[NN * 64];
__device__ float   d_bufC[NN * 64];
__device__ __half2 d_h16[NN * 32];
__device__ float   d_es[NN * 2];
__device__ float   d_ed[NN * 2];
__device__ float   d_pe[ETOT * 2];   // per-edge exp (float2 for H2, float for H1)
__device__ int     d_rowptr[NN + 1];
__device__ int     d_cursor[NN];
__device__ int2    d_cr[ETOT];       // (src, dst) for exp passes
__device__ int     d_soff[ETOT];     // prescaled src*32 for agg gather

// zero-blob: [cnt NN ints][bnacc 320 floats][lookback NB u64]
#define ZBYTES (NN * 4 + 320 * 4 + NB * 8)
__device__ unsigned long long d_zblob[(ZBYTES + 7) / 8];
#define D_CNT   ((int*)d_zblob)
#define D_LOOK  ((unsigned long long*)((char*)d_zblob + NN * 4 + 320 * 4))

__device__ __forceinline__ float lrelu(float x) { return fmaxf(x, 0.2f * x); }

// ------- GEMM body (R4-proven scalar core) + BN input + es/ed + fp16-copy epilogue --
template<int K, int NC, bool BN, int H>
__device__ __forceinline__ void gemm_body(
    int bid,
    const float* __restrict__ X, const float* __restrict__ W,
    const float* __restrict__ asv, const float* __restrict__ adv,
    const float* __restrict__ accIn, const float* __restrict__ g,
    const float* __restrict__ be, float* __restrict__ Hout)
{
    constexpr int CT  = NC / 4;
    constexpr int RT  = 256 / CT;
    constexpr int RPB = RT * 4;
    __shared__ float sW[64 * NC];
    __shared__ float sX[RPB * 64];
    __shared__ float sS[BN ? K : 1];
    __shared__ float sT[BN ? K : 1];

    if (BN) {
        if (threadIdx.x < K) {
            float mu  = accIn[threadIdx.x] * (1.f / NN);
            float var = fmaf(-mu, mu, accIn[K + threadIdx.x] * (1.f / NN));
            float sc  = rsqrtf(var + EPS) * g[threadIdx.x];
            sS[threadIdx.x] = sc;
            sT[threadIdx.x] = be[threadIdx.x] - mu * sc;
        }
    }
    const int ct = threadIdx.x % CT;
    const int rt = threadIdx.x / CT;
    const int r0 = bid * RPB;
    const int row0 = rt * 4;
    float acc[4][4] = {};

    for (int kt = 0; kt < K; kt += 64) {
        __syncthreads();
#pragma unroll
        for (int i = threadIdx.x; i < 64 * NC / 4; i += 256) {
            reinterpret_cast<float4*>(sW)[i] =
                __ldg(reinterpret_cast<const float4*>(W) + (size_t)kt * (NC / 4) + i);
        }
#pragma unroll
        for (int i = threadIdx.x; i < RPB * 16; i += 256) {
            int r = i >> 4, c4 = i & 15;
            int gr = r0 + r;
            float4 v = make_float4(0.f, 0.f, 0.f, 0.f);
            if (gr < NN)
                v = *reinterpret_cast<const float4*>(X + (size_t)gr * K + kt + c4 * 4);
            if (BN) {
                int kk = kt + c4 * 4;
                v.x = fmaxf(fmaf(v.x, sS[kk + 0], sT[kk + 0]), 0.f);
                v.y = fmaxf(fmaf(v.y, sS[kk + 1], sT[kk + 1]), 0.f);
                v.z = fmaxf(fmaf(v.z, sS[kk + 2], sT[kk + 2]), 0.f);
                v.w = fmaxf(fmaf(v.w, sS[kk + 3], sT[kk + 3]), 0.f);
            }
            reinterpret_cast<float4*>(sX)[i] = v;
        }
        __syncthreads();
#pragma unroll 8
        for (int k = 0; k < 64; k += 4) {
            float4 wv0 = *reinterpret_cast<const float4*>(sW + (k + 0) * NC + ct * 4);
            float4 wv1 = *reinterpret_cast<const float4*>(sW + (k + 1) * NC + ct * 4);
            float4 wv2 = *reinterpret_cast<const float4*>(sW + (k + 2) * NC + ct * 4);
            float4 wv3 = *reinterpret_cast<const float4*>(sW + (k + 3) * NC + ct * 4);
#pragma unroll
            for (int i = 0; i < 4; i++) {
                float4 xv = *reinterpret_cast<const float4*>(sX + (row0 + i) * 64 + k);
                acc[i][0] = fmaf(xv.x, wv0.x, acc[i][0]);
                acc[i][1] = fmaf(xv.x, wv0.y, acc[i][1]);
                acc[i][2] = fmaf(xv.x, wv0.z, acc[i][2]);
                acc[i][3] = fmaf(xv.x, wv0.w, acc[i][3]);
                acc[i][0] = fmaf(xv.y, wv1.x, acc[i][0]);
                acc[i][1] = fmaf(xv.y, wv1.y, acc[i][1]);
                acc[i][2] = fmaf(xv.y, wv1.z, acc[i][2]);
                acc[i][3] = fmaf(xv.y, wv1.w, acc[i][3]);
                acc[i][0] = fmaf(xv.z, wv2.x, acc[i][0]);
                acc[i][1] = fmaf(xv.z, wv2.y, acc[i][1]);
                acc[i][2] = fmaf(xv.z, wv2.z, acc[i][2]);
                acc[i][3] = fmaf(xv.z, wv2.w, acc[i][3]);
                acc[i][0] = fmaf(xv.w, wv3.x, acc[i][0]);
                acc[i][1] = fmaf(xv.w, wv3.y, acc[i][1]);
                acc[i][2] = fmaf(xv.w, wv3.z, acc[i][2]);
                acc[i][3] = fmaf(xv.w, wv3.w, acc[i][3]);
            }
        }
    }

    float4 a_s = *reinterpret_cast<const float4*>(asv + ct * 4);
    float4 a_d = *reinterpret_cast<const float4*>(adv + ct * 4);
#pragma unroll
    for (int i = 0; i < 4; i++) {
        int gr = r0 + row0 + i;
        float ps = acc[i][0] * a_s.x + acc[i][1] * a_s.y + acc[i][2] * a_s.z + acc[i][3] * a_s.w;
        float pd = acc[i][0] * a_d.x + acc[i][1] * a_d.y + acc[i][2] * a_d.z + acc[i][3] * a_d.w;
        ps += __shfl_xor_sync(0xffffffffu, ps, 1);
        pd += __shfl_xor_sync(0xffffffffu, pd, 1);
        ps += __shfl_xor_sync(0xffffffffu, ps, 2);
        pd += __shfl_xor_sync(0xffffffffu, pd, 2);
        ps += __shfl_xor_sync(0xffffffffu, ps, 4);
        pd += __shfl_xor_sync(0xffffffffu, pd, 4);
        if (gr < NN) {
            float4 o = make_float4(acc[i][0], acc[i][1], acc[i][2], acc[i][3]);
            *reinterpret_cast<float4*>(Hout + (size_t)gr * NC + ct * 4) = o;
            int hbase = (NC == 64) ? (gr * 32 + ct * 2) : (gr * 16 + ct * 2);
            d_h16[hbase]     = __floats2half2_rn(acc[i][0], acc[i][1]);
            d_h16[hbase + 1] = __floats2half2_rn(acc[i][2], acc[i][3]);
            if ((ct & 7) == 0) {
                int head = (H == 2) ? (ct >> 3) : 0;
                d_es[gr * H + head] = ps;
                d_ed[gr * H + head] = pd;
            }
        }
    }
}

// fused gemm1 + degree count (independent block ranges, co-scheduled)
__global__ void __launch_bounds__(256) gemm1_count_k(
    const float* __restrict__ X, const float* __restrict__ W,
    const float* __restrict__ asv, const float* __restrict__ adv,
    float* __restrict__ Hout, const int* __restrict__ dst)
{
    if (blockIdx.x < GB1) {
        gemm_body<128, 64, false, 2>(blockIdx.x, X, W, asv, adv,
                                     nullptr, nullptr, nullptr, Hout);
    } else {
        int i = (blockIdx.x - GB1) * 256 + threadIdx.x;
        if (i < ETOT) {
            int d = (i < EE) ? __ldg(&dst[i]) : (i - EE);
            atomicAdd(&D_CNT[d], 1);
        }
    }
}

template<int K, int NC, bool BN, int H>
__global__ void __launch_bounds__(256) gemm_k(
    const float* __restrict__ X, const float* __restrict__ W,
    const float* __restrict__ asv, const float* __restrict__ adv,
    const float* __restrict__ accIn, const float* __restrict__ g,
    const float* __restrict__ be, float* __restrict__ Hout)
{
    gemm_body<K, NC, BN, H>(blockIdx.x, X, W, asv, adv, accIn, g, be, Hout);
}

// ---------- single-pass scan (decoupled lookback; 49 blocks, all resident) --------
__global__ void scan_k() {
    __shared__ int wsum[32];
    __shared__ int sprev;
    int bid  = blockIdx.x;
    int g    = bid * 1024 + threadIdx.x;
    int lane = threadIdx.x & 31, wid = threadIdx.x >> 5;
    int v = (g < NN) ? D_CNT[g] : 0;
    int x = v;
#pragma unroll
    for (int o = 1; o < 32; o <<= 1) {
        int t = __shfl_up_sync(0xffffffffu, x, o);
        if (lane >= o) x += t;
    }
    if (lane == 31) wsum[wid] = x;
    __syncthreads();
    if (wid == 0) {
        int w = wsum[lane];
#pragma unroll
        for (int o = 1; o < 32; o <<= 1) {
            int t = __shfl_up_sync(0xffffffffu, w, o);
            if (lane >= o) w += t;
        }
        wsum[lane] = w;
    }
    __syncthreads();
    int incl = x + (wid ? wsum[wid - 1] : 0);
    int total = wsum[31];

    if (threadIdx.x == 0) {
        atomicExch(&D_LOOK[bid], (unsigned long long)(unsigned)total | (1ull << 62));
        long long prev = 0;
        for (int j = bid - 1; j >= 0; ) {
            unsigned long long s;
            do { s = atomicAdd(&D_LOOK[j], 0ull); } while ((s >> 62) == 0);
            prev += (int)(unsigned)(s & 0xffffffffull);
            if ((s >> 62) == 2) break;
            j--;
        }
        atomicExch(&D_LOOK[bid],
                   (unsigned long long)(unsigned)(prev + total) | (2ull << 62));
        sprev = (int)prev;
    }
    __syncthreads();
    int inclg = incl + sprev;
    int excl  = inclg - v;
    if (g < NN) { d_rowptr[g] = excl; d_cursor[g] = excl; }
    if (g == NN - 1) d_rowptr[NN] = inclg;
}

// scatter + fused layer-1 exp (gemm1 already produced es/ed)
__global__ void scatter_k(const int* __restrict__ src, const int* __restrict__ dst) {
    int i = blockIdx.x * 256 + threadIdx.x;
    if (i >= ETOT) return;
    int s, d;
    if (i < EE) { s = __ldg(&src[i]); d = __ldg(&dst[i]); }
    else        { s = i - EE; d = s; }
    int pos = atomicAdd(&d_cursor[d], 1);
    d_cr[pos] = make_int2(s, d);
    d_soff[pos] = s * 32;
    const float2* es2 = reinterpret_cast<const float2*>(d_es);
    const float2* ed2 = reinterpret_cast<const float2*>(d_ed);
    float2 e  = __ldg(&es2[s]);
    float2 dd = __ldg(&ed2[d]);
    float2 p;
    p.x = __expf(lrelu(e.x + dd.x));
    p.y = __expf(lrelu(e.y + dd.y));
    reinterpret_cast<float2*>(d_pe)[pos] = p;
}

// ---------------- edge-parallel exp pass (layers 2,3) ----------------
template<int H>
__global__ void exp_k() {
    int i = blockIdx.x * 256 + threadIdx.x;
    if (i >= ETOT) return;
    int2 cr = __ldg(&d_cr[i]);
    if (H == 2) {
        const float2* es2 = reinterpret_cast<const float2*>(d_es);
        const float2* ed2 = reinterpret_cast<const float2*>(d_ed);
        float2 e = __ldg(&es2[cr.x]);
        float2 d = __ldg(&ed2[cr.y]);
        float2 p;
        p.x = __expf(lrelu(e.x + d.x));
        p.y = __expf(lrelu(e.y + d.y));
        reinterpret_cast<float2*>(d_pe)[i] = p;
    } else {
        d_pe[i] = __expf(lrelu(__ldg(&d_es[cr.x]) + __ldg(&d_ed[cr.y])));
    }
}

// -------- GAT aggregation (warp/node, fp16 gather, prescaled offs) + BN stats -----
template<int H>
__global__ void __launch_bounds__(512) agg_k(const float* __restrict__ bias,
                                             float* __restrict__ out,
                                             float* __restrict__ accOut) {
    __shared__ float red[16][128];
    int w = threadIdx.x >> 5;
    int l = threadIdx.x & 31;
    int node = blockIdx.x * 16 + w;

    if (H == 2) {
        float o0 = 0.f, o1 = 0.f;
        if (node < NN) {
            int beg = __ldg(&d_rowptr[node]);
            int end = __ldg(&d_rowptr[node + 1]);
            const float2* pe2 = reinterpret_cast<const float2*>(d_pe);
            float dn = 0.f, a0 = 0.f, a1 = 0.f;
#pragma unroll 4
            for (int j = beg; j < end; j++) {
                int soff = __ldg(&d_soff[j]);
                float2 p = __ldg(&pe2[j]);
                __half2 hh = __ldg(&d_h16[soff + l]);
                float2 hf = __half22float2(hh);
                float pp = (l < 16) ? p.x : p.y;
                a0 = fmaf(pp, hf.x, a0);
                a1 = fmaf(pp, hf.y, a1);
                dn += pp;
            }
            float inv = 1.f / (dn + 1e-16f);
            float2 bb = __ldg(reinterpret_cast<const float2*>(bias) + l);
            o0 = a0 * inv + bb.x;
            o1 = a1 * inv + bb.y;
            reinterpret_cast<float2*>(out + (size_t)node * 64)[l] =
                make_float2(o0, o1);
        }
        red[w][2 * l]          = o0;
        red[w][2 * l + 1]      = o1;
        red[w][64 + 2 * l]     = o0 * o0;
        red[w][64 + 2 * l + 1] = o1 * o1;
        __syncthreads();
        if (threadIdx.x < 128) {
            float s = 0.f;
#pragma unroll
            for (int i = 0; i < 16; i++) s += red[i][threadIdx.x];
            atomicAdd(&accOut[threadIdx.x], s);
        }
    } else {
        const __half* h16h = reinterpret_cast<const __half*>(d_h16);
        float o = 0.f;
        if (node < NN) {
            int beg = __ldg(&d_rowptr[node]);
            int end = __ldg(&d_rowptr[node + 1]);
            float dn = 0.f, a = 0.f;
#pragma unroll 4
            for (int j = beg; j < end; j++) {
                int soff = __ldg(&d_soff[j]);
                float p = __ldg(&d_pe[j]);
                float hv = __half2float(__ldg(&h16h[soff + l]));
                a = fmaf(p, hv, a);
                dn += p;
            }
            o = a / (dn + 1e-16f) + __ldg(bias + l);
            out[(size_t)node * 32 + l] = o;
        }
        red[w][l]      = o;
        red[w][32 + l] = o * o;
        __syncthreads();
        if (threadIdx.x < 64) {
            float s = 0.f;
#pragma unroll
            for (int i = 0; i < 16; i++) s += red[i][threadIdx.x];
            atomicAdd(&accOut[threadIdx.x], s);
        }
    }
}

// final BN apply + ReLU -> out
__global__ void bnapply3_k(const float* __restrict__ X, const float* __restrict__ acc,
                           const float* __restrict__ g, const float* __restrict__ be,
                           float* __restrict__ Y) {
    int idx = blockIdx.x * 256 + threadIdx.x;
    if (idx >= NN * 32) return;
    int c = idx & 31;
    float mu  = acc[c] * (1.f / NN);
    float var = fmaf(-mu, mu, acc[32 + c] * (1.f / NN));
    float y = (X[idx] - mu) * rsqrtf(var + EPS) * g[c] + be[c];
    Y[idx] = fmaxf(y, 0.f);
}

// ---------------- launch ----------------
static inline int cdiv(int a, int b) { return (a + b - 1) / b; }

extern "C" void kernel_launch(void* const* d_in, const int* in_sizes, int n_in,
                              void* d_out, int out_size) {
    const float* x   = (const float*)d_in[0];
    const float* W1  = (const float*)d_in[1];
    const float* as1 = (const float*)d_in[2];
    const float* ad1 = (const float*)d_in[3];
    const float* b1  = (const float*)d_in[4];
    const float* g1  = (const float*)d_in[5];
    const float* be1 = (const float*)d_in[6];
    const float* W2  = (const float*)d_in[7];
    const float* as2 = (const float*)d_in[8];
    const float* ad2 = (const float*)d_in[9];
    const float* b2  = (const float*)d_in[10];
    const float* g2  = (const float*)d_in[11];
    const float* be2 = (const float*)d_in[12];
    const float* W3  = (const float*)d_in[13];
    const float* as3 = (const float*)d_in[14];
    const float* ad3 = (const float*)d_in[15];
    const float* b3  = (const float*)d_in[16];
    const float* g3  = (const float*)d_in[17];
    const float* be3 = (const float*)d_in[18];
    const int*   ei  = (const int*)d_in[19];
    const int* esrc = ei;
    const int* edst = ei + EE;

    float* bufA; cudaGetSymbolAddress((void**)&bufA, d_bufA);
    float* bufB; cudaGetSymbolAddress((void**)&bufB, d_bufB);
    float* bufC; cudaGetSymbolAddress((void**)&bufC, d_bufC);
    char*  zb;   cudaGetSymbolAddress((void**)&zb,   d_zblob);
    float* bnac = (float*)(zb + NN * 4);
    float* outp = (float*)d_out;

    const int aggBlocks  = cdiv(NN, 16);     // 3125
    const int edgeBlocks = EB;               // 3321

    cudaMemsetAsync(zb, 0, ZBYTES);

    // fused gemm1 + degree count (co-scheduled independent blocks)
    gemm1_count_k<<<GB1 + EB, 256>>>(x, W1, as1, ad1, bufB, edst);
    scan_k<<<NB, 1024>>>();
    scatter_k<<<edgeBlocks, 256>>>(esrc, edst);

    // layer 1 (exp already built in scatter)
    agg_k<2><<<aggBlocks, 512>>>(b1, bufC, bnac + 0);

    // layer 2 (BN1+ReLU fused into X staging)
    gemm_k<64, 64, true, 2><<<cdiv(NN, 64), 256>>>(
        bufC, W2, as2, ad2, bnac + 0, g1, be1, bufB);
    exp_k<2><<<edgeBlocks, 256>>>();
    agg_k<2><<<aggBlocks, 512>>>(b2, bufC, bnac + 128);

    // layer 3 (BN2+ReLU fused into X staging)
    gemm_k<64, 32, true, 1><<<cdiv(NN, 128), 256>>>(
        bufC, W3, as3, ad3, bnac + 128, g2, be2, bufA);
    exp_k<1><<<edgeBlocks, 256>>>();
    agg_k<1><<<aggBlocks, 512>>>(b3, bufC, bnac + 256);
    bnapply3_k<<<cdiv(NN * 32, 256), 256>>>(bufC, bnac + 256, g3, be3, outp);
}